// round 14
// baseline (speedup 1.0000x reference)
#include <cuda_runtime.h>
#include <cuda_bf16.h>
#include <math.h>
#include <stdint.h>

// Problem constants (fixed by setup_inputs)
#define D       512
#define NROWS   4096
#define MREFS   65536
#define TOPK    16
#define NSLICE  16
#define NSL2    (NSLICE * 2)    // two half-lists per row per slice

// Tiling
#define BM      128
#define BN      256
#define KC      64              // bf16 per k-chunk (128 B rows)
#define NCHUNK  (D / KC)        // 8

#define INF_F (__int_as_float(0x7f800000))

// ---------------------------------------------------------------------------
// Scratch (device globals; no allocations allowed)
// ---------------------------------------------------------------------------
__device__ __nv_bfloat16 g_xh[NROWS * D];              // 4 MB  normalized x (bf16)
__device__ __nv_bfloat16 g_rh[(size_t)MREFS * D];      // 64 MB refs (bf16)
__device__ float g_slice[(size_t)NSL2 * NROWS * TOPK]; // 8 MB  sorted half-top-16 lists

// ---------------------------------------------------------------------------
// PTX helpers — family-portable only (harness lowers via compute_103)
// ---------------------------------------------------------------------------
__device__ __forceinline__ uint32_t smem_u32(const void* p) {
    uint32_t a;
    asm("{ .reg .u64 t; cvta.to.shared.u64 t, %1; cvt.u32.u64 %0, t; }"
        : "=r"(a) : "l"(p));
    return a;
}
#define CP_ASYNC16(dst, src) \
    asm volatile("cp.async.cg.shared.global [%0], [%1], 16;" :: "r"(dst), "l"(src))
#define CP_COMMIT()  asm volatile("cp.async.commit_group;" ::: "memory")
#define CP_WAIT(N)   asm volatile("cp.async.wait_group %0;" :: "n"(N) : "memory")

__device__ __forceinline__ void ldsm_x4(uint32_t* r, uint32_t addr) {
    asm volatile("ldmatrix.sync.aligned.m8n8.x4.shared.b16 {%0,%1,%2,%3}, [%4];"
        : "=r"(r[0]), "=r"(r[1]), "=r"(r[2]), "=r"(r[3]) : "r"(addr));
}
__device__ __forceinline__ void mma16816(float* d, const uint32_t* a,
                                         uint32_t b0, uint32_t b1) {
    asm volatile(
        "mma.sync.aligned.m16n8k16.row.col.f32.bf16.bf16.f32 "
        "{%0,%1,%2,%3}, {%4,%5,%6,%7}, {%8,%9}, {%0,%1,%2,%3};"
        : "+f"(d[0]), "+f"(d[1]), "+f"(d[2]), "+f"(d[3])
        : "r"(a[0]), "r"(a[1]), "r"(a[2]), "r"(a[3]), "r"(b0), "r"(b1));
}

// ---------------------------------------------------------------------------
// Kernel A: normalize x rows -> bf16
// ---------------------------------------------------------------------------
__global__ void conv_x_kernel(const float* __restrict__ x) {
    int row = blockIdx.x;
    int tid = threadIdx.x;  // 128
    float4 v = reinterpret_cast<const float4*>(x + (size_t)row * D)[tid];
    float ss = v.x * v.x + v.y * v.y + v.z * v.z + v.w * v.w;
    #pragma unroll
    for (int o = 16; o > 0; o >>= 1) ss += __shfl_xor_sync(0xffffffffu, ss, o);
    __shared__ float red[4];
    __shared__ float s_inv;
    if ((tid & 31) == 0) red[tid >> 5] = ss;
    __syncthreads();
    if (tid == 0) {
        float tot = red[0] + red[1] + red[2] + red[3];
        s_inv = 1.0f / fmaxf(sqrtf(tot), 1e-12f);
    }
    __syncthreads();
    float inv = s_inv;
    __nv_bfloat162 a = __floats2bfloat162_rn(v.x * inv, v.y * inv);
    __nv_bfloat162 b = __floats2bfloat162_rn(v.z * inv, v.w * inv);
    uint2 pk = make_uint2(*(uint32_t*)&a, *(uint32_t*)&b);
    reinterpret_cast<uint2*>(g_xh + (size_t)row * D)[tid] = pk;
}

// ---------------------------------------------------------------------------
// Kernel B: refs fp32 -> bf16 (already L2-normalized)
// ---------------------------------------------------------------------------
__global__ void conv_r_kernel(const float* __restrict__ refs) {
    size_t i = ((size_t)blockIdx.x * blockDim.x + threadIdx.x) * 8;
    float4 a = *reinterpret_cast<const float4*>(refs + i);
    float4 b = *reinterpret_cast<const float4*>(refs + i + 4);
    __nv_bfloat162 p0 = __floats2bfloat162_rn(a.x, a.y);
    __nv_bfloat162 p1 = __floats2bfloat162_rn(a.z, a.w);
    __nv_bfloat162 p2 = __floats2bfloat162_rn(b.x, b.y);
    __nv_bfloat162 p3 = __floats2bfloat162_rn(b.z, b.w);
    uint4 pk = make_uint4(*(uint32_t*)&p0, *(uint32_t*)&p1,
                          *(uint32_t*)&p2, *(uint32_t*)&p3);
    *reinterpret_cast<uint4*>(g_rh + i) = pk;
}

// ---------------------------------------------------------------------------
// Kernel C: bf16 mma.sync GEMM (cos) + fused per-row top-16 of d^2 = 2 - 2 cos
// grid (NROWS/BM, NSLICE), 512 threads (16 warps, 4x4 grid, 32x64 per warp)
// SMEM: A resident 128 KB + 2-stage B ring 64 KB + epilogue stage 34 KB
// ---------------------------------------------------------------------------
#define SM_A      0                         // 8 chunks x 16 KB = 131072
#define SM_B      131072                    // 2 stages x 32 KB
#define SM_EPI    (SM_B + 65536)            // 196608
#define STG_LD    68                        // float stride; 68 = 4*17 keeps float4
                                            // offsets 16B-aligned AND pads vs 64
#define SM_TOTAL  (SM_EPI + BM * STG_LD * 4)   // 231424 B

// swizzled smem byte offset for (row, kbyte) in a [rows x 128B] tile
__device__ __forceinline__ uint32_t swz(int row, int kbyte) {
    return (uint32_t)(row * 128 + (kbyte ^ ((row & 7) << 4)));
}

__global__ void __launch_bounds__(512, 1)
knn_mma_kernel(int nrows, int mrefs) {
    extern __shared__ char smem[];
    const uint32_t sb = smem_u32(smem);
    float* stage = reinterpret_cast<float*>(smem + SM_EPI);

    const int tid  = threadIdx.x;
    const int lane = tid & 31;
    const int wid  = tid >> 5;          // 0..15
    const int wm   = wid >> 2;          // rows wm*32
    const int wn   = wid & 3;           // cols wn*64

    const int row0     = blockIdx.x * BM;
    const int sliceLen = mrefs / NSLICE;           // 4096
    const int slice0   = blockIdx.y * sliceLen;
    const int ntiles   = sliceLen / BN;            // 16
    const int NG       = ntiles * NCHUNK;          // 128

    const __nv_bfloat16* Abase = g_xh + (size_t)row0 * D;

    // per-thread sorted top-16 over its half-columns (tid<256: row tid&127,
    // cols (tid>>7)*32..+31 of each tile-phase)
    float best[TOPK];
    #pragma unroll
    for (int j = 0; j < TOPK; ++j) best[j] = INF_F;

    // ldmatrix lane addressing
    const int a_row_l = lane & 15;
    const int a_kb_l  = (lane >> 4) << 4;
    const int b_row_l = ((lane >> 4) << 3) + (lane & 7);
    const int b_kb_l  = ((lane >> 3) & 1) << 4;
    const int g8  = lane >> 2;          // 0..7
    const int tig = lane & 3;           // 0..3

    float acc[2][8][4];
    #pragma unroll
    for (int mi = 0; mi < 2; ++mi)
        #pragma unroll
        for (int nt = 0; nt < 8; ++nt)
            #pragma unroll
            for (int q = 0; q < 4; ++q) acc[mi][nt][q] = 0.0f;

    // ---- prologue: A resident (8192 x 16B) + B chunk 0, one commit group ----
    #pragma unroll
    for (int i = 0; i < 16; ++i) {
        int idx = tid + i * 512;                // seg id in [chunk][row][seg]
        int ck = idx >> 10, rr = (idx >> 3) & 127, sg = idx & 7;
        uint32_t dst = sb + SM_A + ck * 16384 + swz(rr, sg * 16);
        CP_ASYNC16(dst, Abase + (size_t)rr * D + ck * KC + sg * 8);
    }
    {
        const __nv_bfloat16* Bb = g_rh + (size_t)slice0 * D;
        #pragma unroll
        for (int i = 0; i < 4; ++i) {
            int idx = tid + i * 512;
            int rr = idx >> 3, sg = idx & 7;
            uint32_t dst = sb + SM_B + swz(rr, sg * 16);
            CP_ASYNC16(dst, Bb + (size_t)rr * D + sg * 8);
        }
    }
    CP_COMMIT();

    for (int g = 0; g < NG; ++g) {
        const int c = g & 7;           // k-chunk
        const int s = g & 1;           // B stage

        if (g + 1 < NG) {
            const int gn = g + 1;
            const int tn = gn >> 3, cn = gn & 7, sn = gn & 1;
            const __nv_bfloat16* Bb =
                g_rh + (size_t)(slice0 + tn * BN) * D + cn * KC;
            #pragma unroll
            for (int i = 0; i < 4; ++i) {
                int idx = tid + i * 512;
                int rr = idx >> 3, sg = idx & 7;
                uint32_t dst = sb + SM_B + sn * 32768 + swz(rr, sg * 16);
                CP_ASYNC16(dst, Bb + (size_t)rr * D + sg * 8);
            }
            CP_COMMIT();
            CP_WAIT(1);
        } else {
            CP_WAIT(0);
        }
        __syncthreads();

        // compute chunk: 4 k-steps of m16n8k16 on 32x64 warp tile
        {
            const uint32_t As = sb + SM_A + c * 16384;
            const uint32_t Bs = sb + SM_B + s * 32768;
            #pragma unroll
            for (int ks = 0; ks < 4; ++ks) {
                uint32_t a[2][4], b[4][4];
                #pragma unroll
                for (int mi = 0; mi < 2; ++mi) {
                    int row = wm * 32 + mi * 16 + a_row_l;
                    ldsm_x4(a[mi], As + swz(row, ks * 32 + a_kb_l));
                }
                #pragma unroll
                for (int ng = 0; ng < 4; ++ng) {
                    int row = wn * 64 + ng * 16 + b_row_l;
                    ldsm_x4(b[ng], Bs + swz(row, ks * 32 + b_kb_l));
                }
                #pragma unroll
                for (int mi = 0; mi < 2; ++mi)
                    #pragma unroll
                    for (int nt = 0; nt < 8; ++nt)
                        mma16816(acc[mi][nt], a[mi],
                                 b[nt >> 1][(nt & 1) * 2],
                                 b[nt >> 1][(nt & 1) * 2 + 1]);
            }
        }
        __syncthreads();   // stage s reused by the load issued next iteration

        // ---- tile end: epilogue in 4 phases of 64 columns ----
        if (c == NCHUNK - 1) {
            #pragma unroll
            for (int h = 0; h < 4; ++h) {
                if (wn == h) {
                    #pragma unroll
                    for (int mi = 0; mi < 2; ++mi) {
                        int r = wm * 32 + mi * 16 + g8;
                        #pragma unroll
                        for (int nt = 0; nt < 8; ++nt) {
                            int cc = nt * 8 + 2 * tig;
                            float2 lo = make_float2(
                                fmaf(-2.0f, acc[mi][nt][0], 2.0f),
                                fmaf(-2.0f, acc[mi][nt][1], 2.0f));
                            float2 hi = make_float2(
                                fmaf(-2.0f, acc[mi][nt][2], 2.0f),
                                fmaf(-2.0f, acc[mi][nt][3], 2.0f));
                            *reinterpret_cast<float2*>(&stage[r * STG_LD + cc]) = lo;
                            *reinterpret_cast<float2*>(&stage[(r + 8) * STG_LD + cc]) = hi;
                        }
                    }
                }
                __syncthreads();
                if (tid < 256) {
                    const int r  = tid & 127;
                    const int co = (tid >> 7) * 32;
                    float th = best[TOPK - 1];
                    #pragma unroll
                    for (int i = 0; i < 8; ++i) {
                        float4 v = *reinterpret_cast<const float4*>(
                            &stage[r * STG_LD + co + i * 4]);
                        #pragma unroll
                        for (int e = 0; e < 4; ++e) {
                            float vv = (e == 0) ? v.x : (e == 1) ? v.y
                                       : (e == 2) ? v.z : v.w;
                            if (vv < th) {
                                float cur = vv;
                                #pragma unroll
                                for (int q = 0; q < TOPK; ++q) {
                                    float old = best[q];
                                    best[q] = fminf(old, cur);
                                    cur = fmaxf(old, cur);
                                }
                                th = best[TOPK - 1];
                            }
                        }
                    }
                }
                __syncthreads();
            }
            #pragma unroll
            for (int mi = 0; mi < 2; ++mi)
                #pragma unroll
                for (int nt = 0; nt < 8; ++nt)
                    #pragma unroll
                    for (int q = 0; q < 4; ++q) acc[mi][nt][q] = 0.0f;
        }
    }

    // dump sorted half-lists: slice slot = blockIdx.y*2 + (tid>>7)
    if (tid < 256) {
        const int r  = tid & 127;
        const int sl = blockIdx.y * 2 + (tid >> 7);
        float* dst = &g_slice[((size_t)sl * nrows + row0 + r) * TOPK];
        #pragma unroll
        for (int j = 0; j < TOPK; ++j) dst[j] = best[j];
    }
}

// ---------------------------------------------------------------------------
// Kernel D: merge NSL2 sorted 16-lists per row -> weights
// ---------------------------------------------------------------------------
__global__ void merge_kernel(float* __restrict__ out, int nrows) {
    int r = blockIdx.x * blockDim.x + threadIdx.x;
    if (r >= nrows) return;

    float best[TOPK];
    #pragma unroll
    for (int j = 0; j < TOPK; ++j) best[j] = INF_F;
    float th = INF_F;

    for (int s = 0; s < NSL2; ++s) {
        const float* lst = &g_slice[((size_t)s * nrows + r) * TOPK];
        for (int j = 0; j < TOPK; ++j) {
            float v = lst[j];
            if (v >= th) break;  // lists are sorted ascending
            int p = TOPK - 1;
            while (p > 0 && best[p - 1] > v) { best[p] = best[p - 1]; --p; }
            best[p] = v;
            th = best[TOPK - 1];
        }
    }

    float w[TOPK];
    float sum = 0.0f;
    #pragma unroll
    for (int j = 0; j < TOPK; ++j) {
        float d = sqrtf(fmaxf(best[j], 1e-12f));
        w[j] = expf(-d);
        sum += w[j];
    }
    float inv = 1.0f / fmaxf(sum, 1e-12f);
    #pragma unroll
    for (int j = 0; j < TOPK; ++j) out[(size_t)r * TOPK + j] = w[j] * inv;
}

// ---------------------------------------------------------------------------
extern "C" void kernel_launch(void* const* d_in, const int* in_sizes, int n_in,
                              void* d_out, int out_size) {
    const float* x    = (const float*)d_in[0];
    const float* refs = (const float*)d_in[1];
    float* out        = (float*)d_out;

    int nrows = in_sizes[0] / D;   // 4096
    int mrefs = in_sizes[1] / D;   // 65536

    cudaFuncSetAttribute(knn_mma_kernel,
                         cudaFuncAttributeMaxDynamicSharedMemorySize, SM_TOTAL);

    conv_x_kernel<<<nrows, 128>>>(x);
    conv_r_kernel<<<(unsigned)(((size_t)mrefs * D) / (256 * 8)), 256>>>(refs);

    dim3 g2(nrows / BM, NSLICE);
    knn_mma_kernel<<<g2, 512, SM_TOTAL>>>(nrows, mrefs);

    merge_kernel<<<(nrows + 63) / 64, 64>>>(out, nrows);
}

// round 17
// speedup vs baseline: 1.2354x; 1.2354x over previous
#include <cuda_runtime.h>
#include <cuda_bf16.h>
#include <math.h>
#include <stdint.h>

// Problem constants (fixed by setup_inputs)
#define D       512
#define NROWS   4096
#define MREFS   65536
#define TOPK    16
#define NSLICE  16
#define NSL2    (NSLICE * 2)    // two half-lists per row per slice

// Tiling
#define BM      128
#define BN      128
#define KC      64              // bf16 per k-chunk (128 B rows)
#define NCHUNK  (D / KC)        // 8

#define INF_F    (__int_as_float(0x7f800000))
#define NEGINF_F (__int_as_float(0xff800000))

// ---------------------------------------------------------------------------
// Scratch (device globals; no allocations allowed)
// ---------------------------------------------------------------------------
__device__ __nv_bfloat16 g_xh[NROWS * D];              // 4 MB  normalized x (bf16)
__device__ __nv_bfloat16 g_rh[(size_t)MREFS * D];      // 64 MB refs (bf16)
// row-major: per row, NSL2 sorted 16-lists contiguous (2 KB per row)
__device__ float g_slice[(size_t)NROWS * NSL2 * TOPK]; // 8 MB

// ---------------------------------------------------------------------------
// PTX helpers — family-portable only (harness lowers via compute_103)
// ---------------------------------------------------------------------------
__device__ __forceinline__ uint32_t smem_u32(const void* p) {
    uint32_t a;
    asm("{ .reg .u64 t; cvta.to.shared.u64 t, %1; cvt.u32.u64 %0, t; }"
        : "=r"(a) : "l"(p));
    return a;
}
#define CP_ASYNC16(dst, src) \
    asm volatile("cp.async.cg.shared.global [%0], [%1], 16;" :: "r"(dst), "l"(src))
#define CP_COMMIT()  asm volatile("cp.async.commit_group;" ::: "memory")
#define CP_WAIT(N)   asm volatile("cp.async.wait_group %0;" :: "n"(N) : "memory")

__device__ __forceinline__ void ldsm_x4(uint32_t* r, uint32_t addr) {
    asm volatile("ldmatrix.sync.aligned.m8n8.x4.shared.b16 {%0,%1,%2,%3}, [%4];"
        : "=r"(r[0]), "=r"(r[1]), "=r"(r[2]), "=r"(r[3]) : "r"(addr));
}
__device__ __forceinline__ void mma16816(float* d, const uint32_t* a,
                                         uint32_t b0, uint32_t b1) {
    asm volatile(
        "mma.sync.aligned.m16n8k16.row.col.f32.bf16.bf16.f32 "
        "{%0,%1,%2,%3}, {%4,%5,%6,%7}, {%8,%9}, {%0,%1,%2,%3};"
        : "+f"(d[0]), "+f"(d[1]), "+f"(d[2]), "+f"(d[3])
        : "r"(a[0]), "r"(a[1]), "r"(a[2]), "r"(a[3]), "r"(b0), "r"(b1));
}

// ---------------------------------------------------------------------------
// Kernel A: normalize x rows -> bf16
// ---------------------------------------------------------------------------
__global__ void conv_x_kernel(const float* __restrict__ x) {
    int row = blockIdx.x;
    int tid = threadIdx.x;  // 128
    float4 v = reinterpret_cast<const float4*>(x + (size_t)row * D)[tid];
    float ss = v.x * v.x + v.y * v.y + v.z * v.z + v.w * v.w;
    #pragma unroll
    for (int o = 16; o > 0; o >>= 1) ss += __shfl_xor_sync(0xffffffffu, ss, o);
    __shared__ float red[4];
    __shared__ float s_inv;
    if ((tid & 31) == 0) red[tid >> 5] = ss;
    __syncthreads();
    if (tid == 0) {
        float tot = red[0] + red[1] + red[2] + red[3];
        s_inv = 1.0f / fmaxf(sqrtf(tot), 1e-12f);
    }
    __syncthreads();
    float inv = s_inv;
    __nv_bfloat162 a = __floats2bfloat162_rn(v.x * inv, v.y * inv);
    __nv_bfloat162 b = __floats2bfloat162_rn(v.z * inv, v.w * inv);
    uint2 pk = make_uint2(*(uint32_t*)&a, *(uint32_t*)&b);
    reinterpret_cast<uint2*>(g_xh + (size_t)row * D)[tid] = pk;
}

// ---------------------------------------------------------------------------
// Kernel B: refs fp32 -> bf16 (already L2-normalized)
// ---------------------------------------------------------------------------
__global__ void conv_r_kernel(const float* __restrict__ refs) {
    size_t i = ((size_t)blockIdx.x * blockDim.x + threadIdx.x) * 8;
    float4 a = *reinterpret_cast<const float4*>(refs + i);
    float4 b = *reinterpret_cast<const float4*>(refs + i + 4);
    __nv_bfloat162 p0 = __floats2bfloat162_rn(a.x, a.y);
    __nv_bfloat162 p1 = __floats2bfloat162_rn(a.z, a.w);
    __nv_bfloat162 p2 = __floats2bfloat162_rn(b.x, b.y);
    __nv_bfloat162 p3 = __floats2bfloat162_rn(b.z, b.w);
    uint4 pk = make_uint4(*(uint32_t*)&p0, *(uint32_t*)&p1,
                          *(uint32_t*)&p2, *(uint32_t*)&p3);
    *reinterpret_cast<uint4*>(g_rh + i) = pk;
}

// ---------------------------------------------------------------------------
// Kernel C: bf16 mma.sync GEMM (cos) + fused per-row top-16 (largest cos)
// grid (NROWS/BM, NSLICE), 256 threads (8 warps, 2x4 warp grid, 64x32/warp)
// SMEM 100352 B -> occupancy 2 (the thing R12 broke; protected here)
// ---------------------------------------------------------------------------
#define SM_A      0                       // 2 stages x 16 KB
#define SM_B      32768                   // 2 stages x 16 KB
#define SM_EPI    65536                   // 128 x 68 floats = 34816 B
#define STG_LD    68                      // 4*17: float4-aligned + conflict pad
#define SM_TOTAL  (SM_EPI + BM * STG_LD * 4)

// swizzled smem byte offset for (row, kbyte) in a [128 x 128B] tile
__device__ __forceinline__ uint32_t swz(int row, int kbyte) {
    return (uint32_t)(row * 128 + (kbyte ^ ((row & 7) << 4)));
}

// issue one 128x128B chunk load (1024 x 16B) via cp.async
__device__ __forceinline__ void load_chunk(uint32_t dst_base,
                                           const __nv_bfloat16* src_base, int tid) {
    #pragma unroll
    for (int i = 0; i < 4; ++i) {
        int idx = tid + i * 256;
        int row = idx >> 3, seg = idx & 7;
        uint32_t dst = dst_base + swz(row, seg * 16);
        const void* src = src_base + (size_t)row * D + seg * 8;
        CP_ASYNC16(dst, src);
    }
}

__global__ void __launch_bounds__(256, 2)
knn_mma_kernel(int nrows, int mrefs) {
    extern __shared__ char smem[];
    const uint32_t sb = smem_u32(smem);
    float* stage = reinterpret_cast<float*>(smem + SM_EPI);

    const int tid  = threadIdx.x;
    const int lane = tid & 31;
    const int wid  = tid >> 5;
    const int wm   = wid >> 2;          // 0..1 -> rows wm*64
    const int wn   = wid & 3;           // 0..3 -> cols wn*32

    const int row0     = blockIdx.x * BM;
    const int sliceLen = mrefs / NSLICE;           // 4096
    const int slice0   = blockIdx.y * sliceLen;
    const int ntiles   = sliceLen / BN;            // 32
    const int NG       = ntiles * NCHUNK;          // 256

    const __nv_bfloat16* Abase = g_xh + (size_t)row0 * D;

    // per-thread top-16 LARGEST cos, best[0] = max (descending).
    // thread tid<256 owns row tid&127, column-half tid>>7 of each phase.
    float best[TOPK];
    #pragma unroll
    for (int j = 0; j < TOPK; ++j) best[j] = NEGINF_F;

    // ldmatrix lane addressing
    const int a_row_l = lane & 15;
    const int a_kb_l  = (lane >> 4) << 4;
    const int b_row_l = ((lane >> 4) << 3) + (lane & 7);
    const int b_kb_l  = ((lane >> 3) & 1) << 4;

    float acc[4][4][4];
    #pragma unroll
    for (int mi = 0; mi < 4; ++mi)
        #pragma unroll
        for (int nt = 0; nt < 4; ++nt)
            #pragma unroll
            for (int q = 0; q < 4; ++q) acc[mi][nt][q] = 0.0f;

    // prologue: chunk 0 into stage 0
    load_chunk(sb + SM_A, Abase, tid);
    load_chunk(sb + SM_B, g_rh + (size_t)slice0 * D, tid);
    CP_COMMIT();

    for (int g = 0; g < NG; ++g) {
        const int c = g & 7;           // k-chunk
        const int s = g & 1;           // stage

        if (g + 1 < NG) {
            const int gn = g + 1;
            const int tn = gn >> 3, cn = gn & 7, sn = gn & 1;
            load_chunk(sb + SM_A + sn * 16384, Abase + cn * KC, tid);
            load_chunk(sb + SM_B + sn * 16384,
                       g_rh + (size_t)(slice0 + tn * BN) * D + cn * KC, tid);
            CP_COMMIT();
            CP_WAIT(1);
        } else {
            CP_WAIT(0);
        }
        __syncthreads();

        // compute chunk: 4 k-steps of m16n8k16
        {
            const uint32_t As = sb + SM_A + s * 16384;
            const uint32_t Bs = sb + SM_B + s * 16384;
            #pragma unroll
            for (int ks = 0; ks < 4; ++ks) {
                uint32_t a[4][4], b[2][4];
                #pragma unroll
                for (int mi = 0; mi < 4; ++mi) {
                    int row = wm * 64 + mi * 16 + a_row_l;
                    ldsm_x4(a[mi], As + swz(row, ks * 32 + a_kb_l));
                }
                #pragma unroll
                for (int nip = 0; nip < 2; ++nip) {
                    int row = wn * 32 + nip * 16 + b_row_l;
                    ldsm_x4(b[nip], Bs + swz(row, ks * 32 + b_kb_l));
                }
                #pragma unroll
                for (int mi = 0; mi < 4; ++mi) {
                    #pragma unroll
                    for (int nt = 0; nt < 4; ++nt)
                        mma16816(acc[mi][nt], a[mi],
                                 b[nt >> 1][(nt & 1) * 2],
                                 b[nt >> 1][(nt & 1) * 2 + 1]);
                }
            }
        }
        __syncthreads();   // stage s free for the load issued next iteration

        // ---- tile end: epilogue, 2 phases of 64 cols, raw cos staged ----
        if (c == NCHUNK - 1) {
            const int g8 = lane >> 2, tig = lane & 3;
            #pragma unroll
            for (int h = 0; h < 2; ++h) {
                if ((wn >> 1) == h) {
                    const int wnl = wn & 1;
                    #pragma unroll
                    for (int mi = 0; mi < 4; ++mi) {
                        #pragma unroll
                        for (int nt = 0; nt < 4; ++nt) {
                            int r = wm * 64 + mi * 16 + g8;
                            int cc = wnl * 32 + nt * 8 + 2 * tig;
                            *reinterpret_cast<float2*>(&stage[r * STG_LD + cc]) =
                                make_float2(acc[mi][nt][0], acc[mi][nt][1]);
                            *reinterpret_cast<float2*>(&stage[(r + 8) * STG_LD + cc]) =
                                make_float2(acc[mi][nt][2], acc[mi][nt][3]);
                        }
                    }
                }
                __syncthreads();
                {   // 256 threads scan: row tid&127, cols (tid>>7)*32 .. +31
                    const int r  = tid & 127;
                    const int co = (tid >> 7) * 32;
                    float th = best[TOPK - 1];
                    #pragma unroll
                    for (int i = 0; i < 8; ++i) {
                        float4 v = *reinterpret_cast<const float4*>(
                            &stage[r * STG_LD + co + i * 4]);
                        #pragma unroll
                        for (int e = 0; e < 4; ++e) {
                            float vv = (e == 0) ? v.x : (e == 1) ? v.y
                                       : (e == 2) ? v.z : v.w;
                            if (vv > th) {        // larger cos = closer
                                float cur = vv;
                                #pragma unroll
                                for (int q = 0; q < TOPK; ++q) {
                                    float old = best[q];
                                    best[q] = fmaxf(old, cur);
                                    cur = fminf(old, cur);
                                }
                                th = best[TOPK - 1];
                            }
                        }
                    }
                }
                __syncthreads();
            }
            // reset accumulators for next tile
            #pragma unroll
            for (int mi = 0; mi < 4; ++mi)
                #pragma unroll
                for (int nt = 0; nt < 4; ++nt)
                    #pragma unroll
                    for (int q = 0; q < 4; ++q) acc[mi][nt][q] = 0.0f;
        }
    }

    // dump: convert cos -> d^2 (ascending, since best is descending in cos)
    {
        const int r  = tid & 127;
        const int sl = blockIdx.y * 2 + (tid >> 7);
        float* dst = &g_slice[((size_t)(row0 + r) * NSL2 + sl) * TOPK];
        #pragma unroll
        for (int j = 0; j < TOPK; ++j)
            dst[j] = fmaf(-2.0f, best[j], 2.0f);
    }
}

// ---------------------------------------------------------------------------
// Kernel D: merge NSL2 sorted 16-lists per row -> weights (row-contiguous)
// ---------------------------------------------------------------------------
__global__ void merge_kernel(float* __restrict__ out, int nrows) {
    int r = blockIdx.x * blockDim.x + threadIdx.x;
    if (r >= nrows) return;

    const float* base = &g_slice[(size_t)r * NSL2 * TOPK];

    float best[TOPK];
    #pragma unroll
    for (int j = 0; j < TOPK; ++j) best[j] = INF_F;
    float th = INF_F;

    for (int s = 0; s < NSL2; ++s) {
        const float* lst = base + s * TOPK;
        for (int j = 0; j < TOPK; ++j) {
            float v = lst[j];
            if (v >= th) break;  // lists are sorted ascending
            int p = TOPK - 1;
            while (p > 0 && best[p - 1] > v) { best[p] = best[p - 1]; --p; }
            best[p] = v;
            th = best[TOPK - 1];
        }
    }

    float w[TOPK];
    float sum = 0.0f;
    #pragma unroll
    for (int j = 0; j < TOPK; ++j) {
        float d = sqrtf(fmaxf(best[j], 1e-12f));
        w[j] = expf(-d);
        sum += w[j];
    }
    float inv = 1.0f / fmaxf(sum, 1e-12f);
    #pragma unroll
    for (int j = 0; j < TOPK; ++j) out[(size_t)r * TOPK + j] = w[j] * inv;
}

// ---------------------------------------------------------------------------
extern "C" void kernel_launch(void* const* d_in, const int* in_sizes, int n_in,
                              void* d_out, int out_size) {
    const float* x    = (const float*)d_in[0];
    const float* refs = (const float*)d_in[1];
    float* out        = (float*)d_out;

    int nrows = in_sizes[0] / D;   // 4096
    int mrefs = in_sizes[1] / D;   // 65536

    cudaFuncSetAttribute(knn_mma_kernel,
                         cudaFuncAttributeMaxDynamicSharedMemorySize, SM_TOTAL);

    conv_x_kernel<<<nrows, 128>>>(x);
    conv_r_kernel<<<(unsigned)(((size_t)mrefs * D) / (256 * 8)), 256>>>(refs);

    dim3 g2(nrows / BM, NSLICE);
    knn_mma_kernel<<<g2, 256, SM_TOTAL>>>(nrows, mrefs);

    merge_kernel<<<(nrows + 255) / 256, 256>>>(out, nrows);
}